// round 4
// baseline (speedup 1.0000x reference)
#include <cuda_runtime.h>
#include <cuda_bf16.h>

#define B_SZ   8
#define T_SZ   2048
#define VOCAB  8192
#define NT     1024

__global__ __launch_bounds__(NT)
void constrained_attn_kernel(const int* __restrict__ x,
                             const float* __restrict__ params,
                             float* __restrict__ out)
{
    __shared__ short toks[T_SZ];      // 4 KB
    __shared__ float scores[T_SZ];    // 8 KB
    __shared__ float vocab[VOCAB];    // 32 KB
    __shared__ float red_max[32];
    __shared__ float red_sum[32];

    const int b    = blockIdx.x;
    const int tid  = threadIdx.x;
    const int lane = tid & 31;
    const int warp = tid >> 5;

    // ---- vectorized token load: 2048 ints = 512 int4 ----
    if (tid < T_SZ / 4) {
        const int4 w = reinterpret_cast<const int4*>(x + b * T_SZ)[tid];
        short4 s4;
        s4.x = (short)w.x; s4.y = (short)w.y; s4.z = (short)w.z; s4.w = (short)w.w;
        reinterpret_cast<short4*>(toks)[tid] = s4;
    }

    // ---- vectorized vocab zero: 8192 floats = 2048 float4 ----
    const float4 z4 = make_float4(0.f, 0.f, 0.f, 0.f);
    #pragma unroll
    for (int v = tid; v < VOCAB / 4; v += NT)
        reinterpret_cast<float4*>(vocab)[v] = z4;

    __syncthreads();   // BAR 1

    const int q0 = toks[T_SZ - 1];
    const int q1 = toks[T_SZ - 2];
    const int q2 = toks[T_SZ - 3];

    float p[3][3];
    #pragma unroll
    for (int i = 0; i < 3; i++)
        #pragma unroll
        for (int j = 0; j < 3; j++)
            p[i][j] = params[i * 3 + j];

    // ---- scores + local max (2 tokens per thread) ----
    float lmax = -1e30f;
    #pragma unroll
    for (int it = 0; it < 2; it++) {
        const int t = tid + it * NT;
        float s;
        if (t == T_SZ - 1) {
            s = -1000000000.0f;
        } else {
            const int k0 = toks[t];
            const int k1 = (t >= 1) ? (int)toks[t - 1] : -1;
            const int k2 = (t >= 2) ? (int)toks[t - 2] : -1;
            s  = (q0 == k0) ? p[0][0] : 0.0f;
            s += (q0 == k1) ? p[0][1] : 0.0f;
            s += (q0 == k2) ? p[0][2] : 0.0f;
            s += (q1 == k0) ? p[1][0] : 0.0f;
            s += (q1 == k1) ? p[1][1] : 0.0f;
            s += (q1 == k2) ? p[1][2] : 0.0f;
            s += (q2 == k0) ? p[2][0] : 0.0f;
            s += (q2 == k1) ? p[2][1] : 0.0f;
            s += (q2 == k2) ? p[2][2] : 0.0f;
        }
        scores[t] = s;
        lmax = fmaxf(lmax, s);
    }

    // ---- block max: warp butterfly -> stage -> every warp reduces partials ----
    #pragma unroll
    for (int off = 16; off; off >>= 1)
        lmax = fmaxf(lmax, __shfl_xor_sync(0xffffffffu, lmax, off));
    if (lane == 0) red_max[warp] = lmax;
    __syncthreads();   // BAR 2
    float gmax = red_max[lane];
    #pragma unroll
    for (int off = 16; off; off >>= 1)
        gmax = fmaxf(gmax, __shfl_xor_sync(0xffffffffu, gmax, off));
    // all threads now hold gmax; no extra barrier needed

    // ---- exp + local sum ----
    float lsum = 0.0f;
    #pragma unroll
    for (int it = 0; it < 2; it++) {
        const int t = tid + it * NT;
        const float e = __expf(scores[t] - gmax);
        scores[t] = e;
        lsum += e;
    }

    // ---- block sum: same pattern ----
    #pragma unroll
    for (int off = 16; off; off >>= 1)
        lsum += __shfl_xor_sync(0xffffffffu, lsum, off);
    if (lane == 0) red_sum[warp] = lsum;
    __syncthreads();   // BAR 3
    float gsum = red_sum[lane];
    #pragma unroll
    for (int off = 16; off; off >>= 1)
        gsum += __shfl_xor_sync(0xffffffffu, gsum, off);
    const float inv = 1.0f / gsum;

    // ---- scatter into shared histogram ----
    #pragma unroll
    for (int it = 0; it < 2; it++) {
        const int t = tid + it * NT;
        atomicAdd(&vocab[(int)toks[t]], scores[t] * inv);
    }
    __syncthreads();   // BAR 4

    // ---- vectorized output store: 2048 float4 ----
    float4* ob4 = reinterpret_cast<float4*>(out + b * VOCAB);
    #pragma unroll
    for (int v = tid; v < VOCAB / 4; v += NT)
        ob4[v] = reinterpret_cast<const float4*>(vocab)[v];
}

extern "C" void kernel_launch(void* const* d_in, const int* in_sizes, int n_in,
                              void* d_out, int out_size)
{
    const int*   x      = (const int*)d_in[0];     // (8, 2048) int32
    const float* params = (const float*)d_in[1];   // (3, 3) float32
    float*       out    = (float*)d_out;           // (8, 8192) float32

    (void)in_sizes; (void)n_in; (void)out_size;
    constrained_attn_kernel<<<B_SZ, NT>>>(x, params, out);
}

// round 7
// speedup vs baseline: 1.1381x; 1.1381x over previous
#include <cuda_runtime.h>
#include <cuda_bf16.h>

#define B_SZ   8
#define T_SZ   2048
#define VOCAB  8192
#define NT     1024

__global__ __launch_bounds__(NT)
void constrained_attn_kernel(const int* __restrict__ x,
                             const float* __restrict__ params,
                             float* __restrict__ out)
{
    __shared__ short toks[T_SZ];      // 4 KB
    __shared__ float vocab[VOCAB];    // 32 KB
    __shared__ float red_sum[32];

    const int b    = blockIdx.x;
    const int tid  = threadIdx.x;
    const int lane = tid & 31;
    const int warp = tid >> 5;

    // ---- vectorized token load: 2048 ints = 512 int4 (first 512 threads) ----
    if (tid < T_SZ / 4) {
        const int4 w = reinterpret_cast<const int4*>(x + b * T_SZ)[tid];
        short4 s4;
        s4.x = (short)w.x; s4.y = (short)w.y; s4.z = (short)w.z; s4.w = (short)w.w;
        reinterpret_cast<short4*>(toks)[tid] = s4;
    }

    // params (9 scalar LDG, overlaps with the token load/store latency)
    const float p00 = params[0], p01 = params[1], p02 = params[2];
    const float p10 = params[3], p11 = params[4], p12 = params[5];
    const float p20 = params[6], p21 = params[7], p22 = params[8];

    __syncthreads();   // BAR 1: tokens visible

    const int q0 = toks[T_SZ - 1];
    const int q1 = toks[T_SZ - 2];
    const int q2 = toks[T_SZ - 3];

    // Each thread owns tokens t0=2*tid, t1=2*tid+1.
    // Packed reads: u1 = (toks[t0], toks[t1]), u0 = (toks[t0-2], toks[t0-1]).
    // Sentinel 0xFFFF (> VOCAB) for t<0 neighbors never matches any query.
    const unsigned u1 = reinterpret_cast<const unsigned*>(toks)[tid];
    const unsigned u0 = (tid > 0) ? reinterpret_cast<const unsigned*>(toks)[tid - 1]
                                  : 0xFFFFFFFFu;
    const int a0 = (int)(u0 & 0xFFFFu);   // toks[t0-2]
    const int a1 = (int)(u0 >> 16);       // toks[t0-1]
    const int b0 = (int)(u1 & 0xFFFFu);   // toks[t0]
    const int b1 = (int)(u1 >> 16);       // toks[t1]

    // score(t) = sum_{i,j} p[i][j] * [q_i == toks[t-j]]
    float s0, s1;
    s0  = (q0 == b0) ? p00 : 0.0f;        // t0: keys (b0, a1, a0)
    s0 += (q0 == a1) ? p01 : 0.0f;
    s0 += (q0 == a0) ? p02 : 0.0f;
    s0 += (q1 == b0) ? p10 : 0.0f;
    s0 += (q1 == a1) ? p11 : 0.0f;
    s0 += (q1 == a0) ? p12 : 0.0f;
    s0 += (q2 == b0) ? p20 : 0.0f;
    s0 += (q2 == a1) ? p21 : 0.0f;
    s0 += (q2 == a0) ? p22 : 0.0f;

    s1  = (q0 == b1) ? p00 : 0.0f;        // t1: keys (b1, b0, a1)
    s1 += (q0 == b0) ? p01 : 0.0f;
    s1 += (q0 == a1) ? p02 : 0.0f;
    s1 += (q1 == b1) ? p10 : 0.0f;
    s1 += (q1 == b0) ? p11 : 0.0f;
    s1 += (q1 == a1) ? p12 : 0.0f;
    s1 += (q2 == b1) ? p20 : 0.0f;
    s1 += (q2 == b0) ? p21 : 0.0f;
    s1 += (q2 == a1) ? p22 : 0.0f;

    // No max-shift needed: |s| < sum|p| << 1, masked entry is exactly 0.
    const float e0 = __expf(s0);
    const float e1 = (tid == NT - 1) ? 0.0f : __expf(s1);   // t1==T-1 masked
    float lsum = e0 + e1;

    // ---- vocab zero-fill (2 float4/thread), lands before BAR 2 ----
    const float4 z4 = make_float4(0.f, 0.f, 0.f, 0.f);
    reinterpret_cast<float4*>(vocab)[tid]      = z4;
    reinterpret_cast<float4*>(vocab)[tid + NT] = z4;

    // ---- block sum: warp butterfly -> stage -> BAR -> every warp reduces ----
    #pragma unroll
    for (int off = 16; off; off >>= 1)
        lsum += __shfl_xor_sync(0xffffffffu, lsum, off);
    if (lane == 0) red_sum[warp] = lsum;

    __syncthreads();   // BAR 2: covers red_sum staging AND vocab zero-fill

    float gsum = red_sum[lane];
    #pragma unroll
    for (int off = 16; off; off >>= 1)
        gsum += __shfl_xor_sync(0xffffffffu, gsum, off);
    const float inv = 1.0f / gsum;

    // ---- scatter into shared histogram ----
    atomicAdd(&vocab[b0], e0 * inv);
    atomicAdd(&vocab[b1], e1 * inv);

    __syncthreads();   // BAR 3

    // ---- vectorized output store: 2048 float4 ----
    float4* ob4 = reinterpret_cast<float4*>(out + b * VOCAB);
    ob4[tid]      = reinterpret_cast<const float4*>(vocab)[tid];
    ob4[tid + NT] = reinterpret_cast<const float4*>(vocab)[tid + NT];
}

extern "C" void kernel_launch(void* const* d_in, const int* in_sizes, int n_in,
                              void* d_out, int out_size)
{
    const int*   x      = (const int*)d_in[0];     // (8, 2048) int32
    const float* params = (const float*)d_in[1];   // (3, 3) float32
    float*       out    = (float*)d_out;           // (8, 8192) float32

    (void)in_sizes; (void)n_in; (void)out_size;
    constrained_attn_kernel<<<B_SZ, NT>>>(x, params, out);
}

// round 8
// speedup vs baseline: 1.3077x; 1.1490x over previous
#include <cuda_runtime.h>
#include <cuda_bf16.h>

#define B_SZ    8
#define T_SZ    2048
#define VOCAB   8192
#define NT      1024
#define SPLIT   8                    // CTAs per batch row
#define SLICE   (VOCAB / SPLIT)      // 1024 vocab entries per CTA

__global__ __launch_bounds__(NT)
void constrained_attn_kernel(const int* __restrict__ x,
                             const float* __restrict__ params,
                             float* __restrict__ out)
{
    __shared__ short toks[T_SZ];       // 4 KB
    __shared__ float vslice[SLICE];    // 4 KB (this CTA's vocab slice)
    __shared__ float red_sum[32];

    const int b     = blockIdx.x >> 3;      // batch row
    const int slice = blockIdx.x & 7;       // vocab slice id
    const int tid   = threadIdx.x;
    const int lane  = tid & 31;
    const int warp  = tid >> 5;

    // ---- token load: 2048 ints = 512 int4 (first 512 threads) ----
    if (tid < T_SZ / 4) {
        const int4 w = reinterpret_cast<const int4*>(x + b * T_SZ)[tid];
        short4 s4;
        s4.x = (short)w.x; s4.y = (short)w.y; s4.z = (short)w.z; s4.w = (short)w.w;
        reinterpret_cast<short4*>(toks)[tid] = s4;
    }

    // zero this CTA's vocab slice (1 float per thread) — covered by BAR 1
    vslice[tid] = 0.0f;

    // params (9 scalar LDG, overlap with token-load latency)
    const float p00 = params[0], p01 = params[1], p02 = params[2];
    const float p10 = params[3], p11 = params[4], p12 = params[5];
    const float p20 = params[6], p21 = params[7], p22 = params[8];

    __syncthreads();   // BAR 1: tokens + slice-zero visible

    const int q0 = toks[T_SZ - 1];
    const int q1 = toks[T_SZ - 2];
    const int q2 = toks[T_SZ - 3];

    // Each thread owns tokens t0=2*tid, t1=2*tid+1 (packed 32-bit smem reads).
    const unsigned u1 = reinterpret_cast<const unsigned*>(toks)[tid];
    const unsigned u0 = (tid > 0) ? reinterpret_cast<const unsigned*>(toks)[tid - 1]
                                  : 0xFFFFFFFFu;   // sentinel never matches
    const int a0 = (int)(u0 & 0xFFFFu);   // toks[t0-2]
    const int a1 = (int)(u0 >> 16);       // toks[t0-1]
    const int b0 = (int)(u1 & 0xFFFFu);   // toks[t0]
    const int b1 = (int)(u1 >> 16);       // toks[t1]

    // score(t) = sum_{i,j} p[i][j] * [q_i == toks[t-j]]
    float s0, s1;
    s0  = (q0 == b0) ? p00 : 0.0f;
    s0 += (q0 == a1) ? p01 : 0.0f;
    s0 += (q0 == a0) ? p02 : 0.0f;
    s0 += (q1 == b0) ? p10 : 0.0f;
    s0 += (q1 == a1) ? p11 : 0.0f;
    s0 += (q1 == a0) ? p12 : 0.0f;
    s0 += (q2 == b0) ? p20 : 0.0f;
    s0 += (q2 == a1) ? p21 : 0.0f;
    s0 += (q2 == a0) ? p22 : 0.0f;

    s1  = (q0 == b1) ? p00 : 0.0f;
    s1 += (q0 == b0) ? p01 : 0.0f;
    s1 += (q0 == a1) ? p02 : 0.0f;
    s1 += (q1 == b1) ? p10 : 0.0f;
    s1 += (q1 == b0) ? p11 : 0.0f;
    s1 += (q1 == a1) ? p12 : 0.0f;
    s1 += (q2 == b1) ? p20 : 0.0f;
    s1 += (q2 == b0) ? p21 : 0.0f;
    s1 += (q2 == a1) ? p22 : 0.0f;

    // No max-shift: |s| < sum|p| << 1; masked final token contributes exactly 0.
    const float e0 = __expf(s0);
    const float e1 = (tid == NT - 1) ? 0.0f : __expf(s1);
    float lsum = e0 + e1;

    // ---- block sum (full softmax Z, computed redundantly in every CTA) ----
    #pragma unroll
    for (int off = 16; off; off >>= 1)
        lsum += __shfl_xor_sync(0xffffffffu, lsum, off);
    if (lane == 0) red_sum[warp] = lsum;

    __syncthreads();   // BAR 2

    float gsum = red_sum[lane];
    #pragma unroll
    for (int off = 16; off; off >>= 1)
        gsum += __shfl_xor_sync(0xffffffffu, gsum, off);
    const float inv = 1.0f / gsum;

    // ---- scatter: only tokens in this CTA's vocab slice (expected ~256/CTA) ----
    if ((b0 >> 10) == slice) atomicAdd(&vslice[b0 & (SLICE - 1)], e0 * inv);
    if ((b1 >> 10) == slice) atomicAdd(&vslice[b1 & (SLICE - 1)], e1 * inv);

    __syncthreads();   // BAR 3

    // ---- store this CTA's 4 KB slice (coalesced, 1 float per thread) ----
    out[b * VOCAB + slice * SLICE + tid] = vslice[tid];
}

extern "C" void kernel_launch(void* const* d_in, const int* in_sizes, int n_in,
                              void* d_out, int out_size)
{
    const int*   x      = (const int*)d_in[0];     // (8, 2048) int32
    const float* params = (const float*)d_in[1];   // (3, 3) float32
    float*       out    = (float*)d_out;           // (8, 8192) float32

    (void)in_sizes; (void)n_in; (void)out_size;
    constrained_attn_kernel<<<B_SZ * SPLIT, NT>>>(x, params, out);
}

// round 9
// speedup vs baseline: 1.3140x; 1.0048x over previous
#include <cuda_runtime.h>
#include <cuda_bf16.h>

#define B_SZ    8
#define T_SZ    2048
#define VOCAB   8192
#define NT      1024
#define SPLIT   8                    // CTAs per batch row
#define SLICE   (VOCAB / SPLIT)      // 1024 vocab entries per CTA

__global__ __launch_bounds__(NT)
void constrained_attn_kernel(const int* __restrict__ x,
                             const float* __restrict__ params,
                             float* __restrict__ out)
{
    __shared__ float vslice[SLICE];    // 4 KB — this CTA's vocab slice
    __shared__ float zcorr;            // sparse softmax-Z correction

    const int b     = blockIdx.x >> 3;      // batch row
    const int slice = blockIdx.x & 7;       // vocab slice id
    const int tid   = threadIdx.x;

    const int* xb = x + b * T_SZ;

    // init smem (covered by BAR 1)
    vslice[tid] = 0.0f;
    if (tid == 0) zcorr = 0.0f;

    // ---- direct gmem token reads (no smem staging) ----
    // thread owns t0 = 2*tid, t1 = 2*tid+1
    const int2 cur  = reinterpret_cast<const int2*>(xb)[tid];              // toks[t0], toks[t0+1]
    const int2 prev = (tid > 0) ? reinterpret_cast<const int2*>(xb)[tid-1]
                                : make_int2(-1, -1);                       // sentinels
    const int a0 = prev.x;   // toks[t0-2]
    const int a1 = prev.y;   // toks[t0-1]
    const int b0 = cur.x;    // toks[t0]
    const int b1 = cur.y;    // toks[t1]

    // query tokens (broadcast LDG, all threads same address -> L1 broadcast)
    const int q0 = xb[T_SZ - 1];
    const int q1 = xb[T_SZ - 2];
    const int q2 = xb[T_SZ - 3];

    // params
    const float p00 = params[0], p01 = params[1], p02 = params[2];
    const float p10 = params[3], p11 = params[4], p12 = params[5];
    const float p20 = params[6], p21 = params[7], p22 = params[8];

    // score(t) = sum_{i,j} p[i][j] * [q_i == toks[t-j]]
    float s0, s1;
    s0  = (q0 == b0) ? p00 : 0.0f;        // t0 keys: (b0, a1, a0)
    s0 += (q0 == a1) ? p01 : 0.0f;
    s0 += (q0 == a0) ? p02 : 0.0f;
    s0 += (q1 == b0) ? p10 : 0.0f;
    s0 += (q1 == a1) ? p11 : 0.0f;
    s0 += (q1 == a0) ? p12 : 0.0f;
    s0 += (q2 == b0) ? p20 : 0.0f;
    s0 += (q2 == a1) ? p21 : 0.0f;
    s0 += (q2 == a0) ? p22 : 0.0f;

    s1  = (q0 == b1) ? p00 : 0.0f;        // t1 keys: (b1, b0, a1)
    s1 += (q0 == b0) ? p01 : 0.0f;
    s1 += (q0 == a1) ? p02 : 0.0f;
    s1 += (q1 == b1) ? p10 : 0.0f;
    s1 += (q1 == b0) ? p11 : 0.0f;
    s1 += (q1 == a1) ? p12 : 0.0f;
    s1 += (q2 == b1) ? p20 : 0.0f;
    s1 += (q2 == b0) ? p21 : 0.0f;
    s1 += (q2 == a1) ? p22 : 0.0f;

    const bool masked1 = (tid == NT - 1);   // t1 == T-1 is masked out

    // exp(0) == 1 exactly, so Z = 2047 + sum over matched tokens of (exp(s)-1).
    // Matches are rare (~8/row): predicated single-address smem atomic
    // (ptxas REDUX-aggregates per warp).
    const float e0 = __expf(s0);
    const float e1 = masked1 ? 0.0f : __expf(s1);
    float corr = 0.0f;
    if (s0 != 0.0f)             corr += e0 - 1.0f;
    if (s1 != 0.0f && !masked1) corr += e1 - 1.0f;
    if (corr != 0.0f) atomicAdd(&zcorr, corr);

    __syncthreads();   // BAR 1: zcorr complete + vslice zero visible

    const float inv = __fdividef(1.0f, 2047.0f + zcorr);

    // ---- scatter: only tokens in this CTA's vocab slice (~256/CTA) ----
    if ((b0 >> 10) == slice)             atomicAdd(&vslice[b0 & (SLICE - 1)], e0 * inv);
    if ((b1 >> 10) == slice && !masked1) atomicAdd(&vslice[b1 & (SLICE - 1)], e1 * inv);

    __syncthreads();   // BAR 2

    // ---- store this CTA's 4 KB slice (coalesced) ----
    out[b * VOCAB + slice * SLICE + tid] = vslice[tid];
}

extern "C" void kernel_launch(void* const* d_in, const int* in_sizes, int n_in,
                              void* d_out, int out_size)
{
    const int*   x      = (const int*)d_in[0];     // (8, 2048) int32
    const float* params = (const float*)d_in[1];   // (3, 3) float32
    float*       out    = (float*)d_out;           // (8, 8192) float32

    (void)in_sizes; (void)n_in; (void)out_size;
    constrained_attn_kernel<<<B_SZ * SPLIT, NT>>>(x, params, out);
}